// round 14
// baseline (speedup 1.0000x reference)
#include <cuda_runtime.h>
#include <cuda_bf16.h>
#include <cuda_fp16.h>
#include <cstdint>
#include <math.h>

#define EPSF 1e-7f
#define BATCH 256

// ---------------- scratch (device globals: no cudaMalloc allowed) ----------------
__device__ float g_x1f[BATCH * 400 * 256];            // conv1 out fp32  105 MB
__device__ signed char g_xq1[BATCH * 400 * 256];      // conv1 digit1 (int8)
__device__ signed char g_xq2[BATCH * 400 * 256];      // conv1 digit2
__device__ signed char g_wq1[256 * 20736];            // pc weights^T digit1
__device__ signed char g_wq2[256 * 20736];            // pc weights^T digit2
__device__ unsigned g_maxA_bits, g_maxB_bits;
__device__ float g_u[9216 * 256];                     // primary caps (fp32)
__device__ __half g_uhath[BATCH * 1152 * 160];        // u_hat fp16    94 MB
__device__ float g_h0[BATCH * 160];
__device__ float g_h1[BATCH * 512];
__device__ float g_h2[BATCH * 1024];

// ======================= helpers (base-sm_100 features only) =======================
__device__ __forceinline__ uint32_t smem_u32(const void* p) {
    uint32_t a;
    asm("{ .reg .u64 t; cvta.to.shared.u64 t, %1; cvt.u32.u64 %0, t; }" : "=r"(a) : "l"(p));
    return a;
}
__device__ __forceinline__ void cp16(uint32_t dst, const void* src) {
    asm volatile("cp.async.cg.shared.global [%0], [%1], 16;" :: "r"(dst), "l"(src) : "memory");
}
__device__ __forceinline__ void ldsm4(int* r, uint32_t addr) {
    asm volatile("ldmatrix.sync.aligned.m8n8.x4.shared.b16 {%0,%1,%2,%3}, [%4];"
                 : "=r"(r[0]), "=r"(r[1]), "=r"(r[2]), "=r"(r[3]) : "r"(addr));
}
__device__ __forceinline__ void mma_s8(int* c, const int* a, int b0, int b1) {
    asm volatile(
        "mma.sync.aligned.m16n8k32.row.col.s32.s8.s8.s32 "
        "{%0,%1,%2,%3}, {%4,%5,%6,%7}, {%8,%9}, {%0,%1,%2,%3};"
        : "+r"(c[0]), "+r"(c[1]), "+r"(c[2]), "+r"(c[3])
        : "r"(a[0]), "r"(a[1]), "r"(a[2]), "r"(a[3]), "r"(b0), "r"(b1));
}
// packed f32x2 (compiles for base sm_100 — verified in round 3)
__device__ __forceinline__ unsigned long long pack2(float x) {
    unsigned long long r;
    asm("mov.b64 %0, {%1, %1};" : "=l"(r) : "f"(x));
    return r;
}
__device__ __forceinline__ unsigned long long fma2(unsigned long long a,
                                                   unsigned long long b,
                                                   unsigned long long c) {
    unsigned long long d;
    asm("fma.rn.f32x2 %0, %1, %2, %3;" : "=l"(d) : "l"(a), "l"(b), "l"(c));
    return d;
}
__device__ __forceinline__ float2 unpk2(unsigned long long v) {
    float2 r;
    asm("mov.b64 {%0, %1}, %2;" : "=f"(r.x), "=f"(r.y) : "l"(v));
    return r;
}

// =====================================================================
// Kernel 0: reset per-launch reductions
// =====================================================================
__global__ void init_kernel() { g_maxA_bits = 0u; g_maxB_bits = 0u; }

// =====================================================================
// Kernel 1 (fused): blocks 0-511 conv1 9x9+ReLU (f32x2 pixel pairs) + maxA;
//                   blocks 512-639 maxB scan over pc weights.
// =====================================================================
__global__ __launch_bounds__(256) void conv1_maxB_kernel(
    const float* __restrict__ x, const float* __restrict__ w,
    const float* __restrict__ bias, const float* __restrict__ pcw)
{
    __shared__ __align__(16) float img[784];
    __shared__ __align__(16) float imgs[784];   // imgs[t] = img[t+1]

    if (blockIdx.x >= 512) {
        float lmax = 0.f;
        for (size_t i = (size_t)(blockIdx.x - 512) * 256 + threadIdx.x; i < 5308416u;
             i += 128u * 256u)
            lmax = fmaxf(lmax, fabsf(pcw[i]));
        atomicMax(&g_maxB_bits, __float_as_uint(lmax));
        return;
    }

    const int b = blockIdx.x >> 1;
    const int half = blockIdx.x & 1;
    const int c = threadIdx.x;

    for (int t = threadIdx.x; t < 784; t += 256) {
        const float v = x[b * 784 + t];
        img[t] = v;
        if (t > 0) imgs[t - 1] = v;
    }
    if (threadIdx.x == 0) imgs[783] = 0.f;

    unsigned long long wr2[81];
#pragma unroll
    for (int k = 0; k < 81; k++) wr2[k] = pack2(w[k * 256 + c]);
    const unsigned long long bias2 = pack2(bias[c]);
    __syncthreads();

    float lmax = 0.f;
    const int oy0 = half * 10;
    for (int oy = oy0; oy < oy0 + 10; oy++) {
        for (int oxp = 0; oxp < 10; oxp++) {
            const int base = oy * 28 + oxp * 2;
            unsigned long long acc0 = bias2, acc1 = pack2(0.f);
#pragma unroll
            for (int ky = 0; ky < 9; ky++) {
                const int ro = base + ky * 28;
#pragma unroll
                for (int kx = 0; kx < 9; kx++) {
                    unsigned long long iv;
                    if ((kx & 1) == 0)
                        iv = *(const unsigned long long*)(img + ro + kx);
                    else
                        iv = *(const unsigned long long*)(imgs + ro + kx - 1);
                    if (ky < 4) acc0 = fma2(wr2[ky * 9 + kx], iv, acc0);
                    else        acc1 = fma2(wr2[ky * 9 + kx], iv, acc1);
                }
            }
            const float2 a0 = unpk2(acc0);
            const float2 a1 = unpk2(acc1);
            const float v0 = fmaxf(a0.x + a1.x, 0.f);
            const float v1 = fmaxf(a0.y + a1.y, 0.f);
            lmax = fmaxf(lmax, fmaxf(v0, v1));
            const size_t pix = (size_t)(b * 20 + oy) * 20 + oxp * 2;
            g_x1f[pix * 256 + c] = v0;
            g_x1f[(pix + 1) * 256 + c] = v1;
        }
    }
    atomicMax(&g_maxA_bits, __float_as_uint(lmax));
}

// =====================================================================
// Kernel 1c (fused): blocks 0-25599 quantize conv1 output -> two int8 digits;
//                    blocks 25600+ transpose+quantize pc weights.
// =====================================================================
__global__ __launch_bounds__(256) void quant_kernel(const float* __restrict__ w)
{
    __shared__ float tile[32][33];
    const int tid = threadIdx.x;

    if (blockIdx.x < 25600) {
        const float maxA = __uint_as_float(g_maxA_bits);
        const float invq = 16383.f / fmaxf(maxA, 1e-20f);
        const size_t i0 = ((size_t)blockIdx.x * 256 + tid) * 4;
        const float4 v = *(const float4*)(g_x1f + i0);
        char4 d1, d2;
        {
            float q = v.x * invq; int a1 = min(127, __float2int_rn(q * 0.0078125f));
            d1.x = (signed char)a1; d2.x = (signed char)__float2int_rn(q - 128.f * a1);
        }
        {
            float q = v.y * invq; int a1 = min(127, __float2int_rn(q * 0.0078125f));
            d1.y = (signed char)a1; d2.y = (signed char)__float2int_rn(q - 128.f * a1);
        }
        {
            float q = v.z * invq; int a1 = min(127, __float2int_rn(q * 0.0078125f));
            d1.z = (signed char)a1; d2.z = (signed char)__float2int_rn(q - 128.f * a1);
        }
        {
            float q = v.w * invq; int a1 = min(127, __float2int_rn(q * 0.0078125f));
            d1.w = (signed char)a1; d2.w = (signed char)__float2int_rn(q - 128.f * a1);
        }
        *(char4*)(g_xq1 + i0) = d1;
        *(char4*)(g_xq2 + i0) = d2;
        return;
    }

    const int q = blockIdx.x - 25600;            // 0 .. 5183
    const int k0 = (q % 648) * 32, n0 = (q / 648) * 32;
    const int tx = tid & 31, ty = tid >> 5;
    const float maxB = __uint_as_float(g_maxB_bits);
    const float invq = 16383.f / fmaxf(maxB, 1e-20f);
#pragma unroll
    for (int r = 0; r < 4; r++)
        tile[ty + 8 * r][tx] = w[(size_t)(k0 + ty + 8 * r) * 256 + n0 + tx];
    __syncthreads();
#pragma unroll
    for (int r = 0; r < 4; r++) {
        const float qv = tile[tx][ty + 8 * r] * invq;
        int b1 = max(-127, min(127, __float2int_rn(qv * 0.0078125f)));
        int b2 = __float2int_rn(qv - 128.f * b1);
        const size_t off = (size_t)(n0 + ty + 8 * r) * 20736 + k0 + tx;
        g_wq1[off] = (signed char)b1;
        g_wq2[off] = (signed char)b2;
    }
}

// =====================================================================
// Kernel 2: primary-caps conv — int8 two-digit mma.sync GEMM.
// M=9216 N=256 K=20736. BM=128 BN=128, K=64/stage, 324 stages.
// 512 threads = 16 warps (4m x 4n), warp tile 32x32 -> 4 warps/SMSP
// to hide ldsm latency (R13 ncu: tensor 46%, occ 12.5% with 8 warps).
// 4-stage cp.async ring (160KB), ONE __syncthreads per stage.
// C1 = A1*B1 ; C2 = A1*B2 + A2*B1.  u = sA*sB*(16384*C1 + 128*C2).
// =====================================================================
#define PC_STAGE 40960
#define PC_NSTAGE 4

#define PC_ISSUE(s_) do {                                                   \
    const int k_ = (s_) * 64;                                               \
    const int ky_ = k_ / 2304;                                              \
    const int off_ = isB ? k_ : (ky_ * 5120 + (k_ - ky_ * 2304));           \
    const uint32_t dst_ = sb + ((s_) % PC_NSTAGE) * PC_STAGE + dstOff;      \
    const signed char* s0_ = srcPtr + off_;                                 \
    cp16(dst_ + 0,  s0_ + 0);  cp16(dst_ + 16, s0_ + 16);                   \
    cp16(dst_ + 32, s0_ + 32); cp16(dst_ + 48, s0_ + 48);                   \
} while (0)

extern __shared__ __align__(128) unsigned char pc_smem[];

__global__ __launch_bounds__(512, 1) void pc_kernel(const float* __restrict__ bias)
{
    const uint32_t sb = smem_u32(pc_smem);
    const int tid = threadIdx.x;
    const int wid = tid >> 5;
    const int lane = tid & 31;
    const int mblock = blockIdx.x * 128;
    const int nbase = blockIdx.y * 128;
    const int warp_m = (wid >> 2) * 32;   // 4 m-groups of 32 rows
    const int warp_n = (wid & 3) * 32;    // 4 n-groups of 32 cols

    // ---- loader mapping: thread = (slab = tid>>7, row = tid&127), 64B each ----
    const int slab = tid >> 7;            // 0:A1 1:A2 2:B1 3:B2
    const int r1 = tid & 127;
    const int isB = slab >> 1;
    const int m = mblock + r1;
    const int bimg = m / 36, p = m % 36;
    const int aBase = bimg * 102400 + (p / 6) * 10240 + (p % 6) * 512;
    const signed char* srcPtr;
    if (slab == 0)      srcPtr = g_xq1 + aBase;
    else if (slab == 1) srcPtr = g_xq2 + aBase;
    else if (slab == 2) srcPtr = g_wq1 + (size_t)(nbase + r1) * 20736;
    else                srcPtr = g_wq2 + (size_t)(nbase + r1) * 20736;
    const uint32_t dstOff = (uint32_t)(slab * 10240 + r1 * 80);

    // ---- ldmatrix per-lane row addresses ----
    const int sel = lane >> 3, l7 = lane & 7;
    const uint32_t aL = (uint32_t)((warp_m + (sel & 1) * 8 + l7) * 80 + (sel >> 1) * 16);
    const uint32_t bL = (uint32_t)(20480 + (warp_n + (sel >> 1) * 8 + l7) * 80 + (sel & 1) * 16);

    int C1[2][4][4], C2[2][4][4];
#pragma unroll
    for (int mt = 0; mt < 2; mt++)
#pragma unroll
        for (int nt = 0; nt < 4; nt++)
#pragma unroll
            for (int q = 0; q < 4; q++) { C1[mt][nt][q] = 0; C2[mt][nt][q] = 0; }

    PC_ISSUE(0);
    asm volatile("cp.async.commit_group;" ::: "memory");
    PC_ISSUE(1);
    asm volatile("cp.async.commit_group;" ::: "memory");

    for (int s = 0; s < 324; s++) {
        if (s + 2 < 324) PC_ISSUE(s + 2);
        asm volatile("cp.async.commit_group;" ::: "memory");
        asm volatile("cp.async.wait_group 2;" ::: "memory");
        __syncthreads();

        const uint32_t st = sb + (uint32_t)(s % PC_NSTAGE) * PC_STAGE;

#pragma unroll
        for (int kk = 0; kk < 2; kk++) {
            int a1f[2][4], a2f[2][4], b1f[2][4], b2f[2][4];
#pragma unroll
            for (int mt = 0; mt < 2; mt++) {
                ldsm4(a1f[mt], st + aL + mt * 1280 + kk * 32);
                ldsm4(a2f[mt], st + 10240 + aL + mt * 1280 + kk * 32);
            }
#pragma unroll
            for (int ntp = 0; ntp < 2; ntp++) {
                ldsm4(b1f[ntp], st + bL + ntp * 1280 + kk * 32);
                ldsm4(b2f[ntp], st + 10240 + bL + ntp * 1280 + kk * 32);
            }
#pragma unroll
            for (int nt = 0; nt < 4; nt++) {
                const int ntp = nt >> 1, ix = (nt & 1) * 2;
                const int b1r0 = b1f[ntp][ix], b1r1 = b1f[ntp][ix + 1];
                const int b2r0 = b2f[ntp][ix], b2r1 = b2f[ntp][ix + 1];
#pragma unroll
                for (int mt = 0; mt < 2; mt++) {
                    mma_s8(C1[mt][nt], a1f[mt], b1r0, b1r1);
                    mma_s8(C2[mt][nt], a1f[mt], b2r0, b2r1);
                    mma_s8(C2[mt][nt], a2f[mt], b1r0, b1r1);
                }
            }
        }
    }

    const float maxA = __uint_as_float(g_maxA_bits);
    const float maxB = __uint_as_float(g_maxB_bits);
    const float sc = (maxA / 16383.f) * (maxB / 16383.f);
    const float f1 = sc * 16384.f, f2 = sc * 128.f;
    const int gID = lane >> 2, tg = lane & 3;
#pragma unroll
    for (int nt = 0; nt < 4; nt++) {
        const int col = nbase + warp_n + nt * 8 + tg * 2;
        const float b0 = bias[col], b1 = bias[col + 1];
#pragma unroll
        for (int mt = 0; mt < 2; mt++) {
            const int row = mblock + warp_m + mt * 16 + gID;
            const int* c1 = C1[mt][nt];
            const int* c2 = C2[mt][nt];
            float2 o0 = make_float2(f1 * c1[0] + f2 * c2[0] + b0,
                                    f1 * c1[1] + f2 * c2[1] + b1);
            float2 o1 = make_float2(f1 * c1[2] + f2 * c2[2] + b0,
                                    f1 * c1[3] + f2 * c2[3] + b1);
            *(float2*)(g_u + (size_t)row * 256 + col) = o0;
            *(float2*)(g_u + (size_t)(row + 8) * 256 + col) = o1;
        }
    }
}

// =====================================================================
// Kernel 3: u_hat -> fp16, 2-way b-ILP
// =====================================================================
__global__ __launch_bounds__(320) void uhat_kernel(const float* __restrict__ wp)
{
    __shared__ float Ws[1280];
    const int i = blockIdx.x;
    const int tid = threadIdx.x;
    for (int t = tid; t < 1280; t += 320) Ws[t] = wp[(size_t)i * 1280 + t];
    __syncthreads();

    const int blane = tid / 40;
    const int jkg = tid - blane * 40;

    float w[32];
#pragma unroll
    for (int q = 0; q < 4; q++)
#pragma unroll
        for (int mm = 0; mm < 8; mm++) w[q * 8 + mm] = Ws[(jkg * 4 + q) * 8 + mm];

    const float* ubase = g_u + (size_t)i * 8;
    __half* obase = g_uhath + (size_t)i * 160 + jkg * 4;

    for (int it = 0; it < 16; it++) {
        const int bA = it * 16 + blane;
        const int bB = bA + 8;
        const float4 uA0 = *(const float4*)(ubase + (size_t)bA * 9216);
        const float4 uA1 = *(const float4*)(ubase + (size_t)bA * 9216 + 4);
        const float4 uB0 = *(const float4*)(ubase + (size_t)bB * 9216);
        const float4 uB1 = *(const float4*)(ubase + (size_t)bB * 9216 + 4);
        float rA[4], rB[4];
#pragma unroll
        for (int q = 0; q < 4; q++) {
            const float* wq = w + q * 8;
            rA[q] = wq[0] * uA0.x + wq[1] * uA0.y + wq[2] * uA0.z + wq[3] * uA0.w +
                    wq[4] * uA1.x + wq[5] * uA1.y + wq[6] * uA1.z + wq[7] * uA1.w;
            rB[q] = wq[0] * uB0.x + wq[1] * uB0.y + wq[2] * uB0.z + wq[3] * uB0.w +
                    wq[4] * uB1.x + wq[5] * uB1.y + wq[6] * uB1.z + wq[7] * uB1.w;
        }
        __half2* opA = (__half2*)(obase + (size_t)bA * 184320);
        __half2* opB = (__half2*)(obase + (size_t)bB * 184320);
        opA[0] = __floats2half2_rn(rA[0], rA[1]);
        opA[1] = __floats2half2_rn(rA[2], rA[3]);
        opB[0] = __floats2half2_rn(rB[0], rB[1]);
        opB[1] = __floats2half2_rn(rB[2], rB[3]);
    }
}

// =====================================================================
// Kernel 4: routing — 3 fused passes; u_hat (fp16) read ONCE per iteration.
// =====================================================================
__device__ __forceinline__ void reduce_squash(
    const float acc[10], int tid, int g, int k,
    float red[32][160], float* sbuf, float* coef, float* vdst, float scale)
{
#pragma unroll
    for (int j = 0; j < 10; j++) red[g][j * 16 + k] = acc[j];
    __syncthreads();
    if (tid < 160) {
        float s = 0.f;
#pragma unroll
        for (int g2 = 0; g2 < 32; g2++) s += red[g2][tid];
        sbuf[tid] = s * scale;
    }
    __syncthreads();
    if (tid < 10) {
        float sn2 = 0.f;
#pragma unroll
        for (int kk = 0; kk < 16; kk++) { const float t = sbuf[tid * 16 + kk]; sn2 += t * t; }
        coef[tid] = sn2 / ((1.f + sn2) * (sqrtf(sn2) + EPSF));
    }
    __syncthreads();
    if (tid < 160) vdst[tid] = coef[tid >> 4] * sbuf[tid];
    __syncthreads();
}

__global__ __launch_bounds__(512, 2) void routing_kernel(
    const float* __restrict__ y, float* __restrict__ vout)
{
    __shared__ float red[32][160];
    __shared__ float sbuf[160];
    __shared__ float coef[10];
    __shared__ float v0[160];
    __shared__ float vcur[160];

    const int b = blockIdx.x;
    const int tid = threadIdx.x;
    const int g = tid >> 4, k = tid & 15;
    const __half* uh = g_uhath + (size_t)b * 184320;

    float acc[10];

#pragma unroll
    for (int j = 0; j < 10; j++) acc[j] = 0.f;
    for (int i = g; i < 1152; i += 32) {
        const __half* r = uh + (size_t)i * 160 + k;
#pragma unroll
        for (int j = 0; j < 10; j++) acc[j] += __half2float(r[j * 16]);
    }
    reduce_squash(acc, tid, g, k, red, sbuf, coef, v0, 0.1f);
    if (tid < 160) vcur[tid] = v0[tid];
    __syncthreads();

    for (int pass = 0; pass < 2; pass++) {
        float vr[10];
#pragma unroll
        for (int j = 0; j < 10; j++) vr[j] = vcur[j * 16 + k];
#pragma unroll
        for (int j = 0; j < 10; j++) acc[j] = 0.f;

        for (int i = g; i < 1152; i += 32) {
            const __half* r = uh + (size_t)i * 160 + k;
            float u[10], a[10];
#pragma unroll
            for (int j = 0; j < 10; j++) u[j] = __half2float(r[j * 16]);
#pragma unroll
            for (int j = 0; j < 10; j++) {
                float d = u[j] * vr[j];
                d += __shfl_xor_sync(0xffffffffu, d, 1);
                d += __shfl_xor_sync(0xffffffffu, d, 2);
                d += __shfl_xor_sync(0xffffffffu, d, 4);
                d += __shfl_xor_sync(0xffffffffu, d, 8);
                a[j] = d;
            }
            float mx = a[0];
#pragma unroll
            for (int j = 1; j < 10; j++) mx = fmaxf(mx, a[j]);
            float sum = 0.f;
#pragma unroll
            for (int j = 0; j < 10; j++) { a[j] = __expf(a[j] - mx); sum += a[j]; }
            const float inv = __fdividef(1.f, sum);
#pragma unroll
            for (int j = 0; j < 10; j++) acc[j] += a[j] * inv * u[j];
        }
        reduce_squash(acc, tid, g, k, red, sbuf, coef, vcur, 1.f);
        if (pass == 0) {
            if (tid < 160) vcur[tid] += v0[tid];
            __syncthreads();
        }
    }

    if (tid < 160) {
        const float v = vcur[tid];
        vout[(size_t)b * 160 + tid] = v;
        g_h0[(size_t)b * 160 + tid] = y[b * 10 + (tid >> 4)] * v;
    }
}

// =====================================================================
// Kernel 5-7: decoder GEMMs — BM=32, BN=64
// =====================================================================
template <int K, int N, int ACT>
__device__ __forceinline__ void gemm_body(
    const float* __restrict__ A, const float* __restrict__ W,
    const float* __restrict__ bias, float* __restrict__ C)
{
    __shared__ float As[16][36];
    __shared__ float Bs[16][68];
    const int tid = threadIdx.x;
    const int n0 = blockIdx.x * 64;
    const int m0 = blockIdx.y * 32;
    const int ty = tid >> 4, tx = tid & 15;
    const int ar = tid >> 3, ak = (tid & 7) * 2;
    const int bk = tid >> 4, bc = (tid & 15) * 4;

    float acc[2][4];
#pragma unroll
    for (int r = 0; r < 2; r++)
#pragma unroll
        for (int q = 0; q < 4; q++) acc[r][q] = 0.f;

    for (int k0 = 0; k0 < K; k0 += 16) {
        const float2 av = *(const float2*)(A + (size_t)(m0 + ar) * K + k0 + ak);
        float4 bv = make_float4(0.f, 0.f, 0.f, 0.f);
        if (n0 + bc < N) bv = *(const float4*)(W + (size_t)(k0 + bk) * N + n0 + bc);
        __syncthreads();
        As[ak][ar] = av.x;
        As[ak + 1][ar] = av.y;
        *(float4*)&Bs[bk][bc] = bv;
        __syncthreads();
#pragma unroll
        for (int kk = 0; kk < 16; kk++) {
            const float a0 = As[kk][ty * 2];
            const float a1 = As[kk][ty * 2 + 1];
            const float4 b4 = *(const float4*)&Bs[kk][tx * 4];
            const float bb[4] = {b4.x, b4.y, b4.z, b4.w};
#pragma unroll
            for (int q = 0; q < 4; q++) {
                acc[0][q] += a0 * bb[q];
                acc[1][q] += a1 * bb[q];
            }
        }
    }

    if (n0 + tx * 4 < N) {
        const float4 bv = *(const float4*)(bias + n0 + tx * 4);
        const float bb[4] = {bv.x, bv.y, bv.z, bv.w};
#pragma unroll
        for (int r = 0; r < 2; r++) {
            const int mm = m0 + ty * 2 + r;
            float o[4];
#pragma unroll
            for (int q = 0; q < 4; q++) {
                float v = acc[r][q] + bb[q];
                if (ACT == 0) v = fmaxf(v, 0.f);
                else          v = 1.f / (1.f + __expf(-v));
                o[q] = v;
            }
            *(float4*)(C + (size_t)mm * N + n0 + tx * 4) = make_float4(o[0], o[1], o[2], o[3]);
        }
    }
}

__global__ __launch_bounds__(256) void dec1_kernel(const float* __restrict__ W,
                                                   const float* __restrict__ b)
{ gemm_body<160, 512, 0>(g_h0, W, b, g_h1); }

__global__ __launch_bounds__(256) void dec2_kernel(const float* __restrict__ W,
                                                   const float* __restrict__ b)
{ gemm_body<512, 1024, 0>(g_h1, W, b, g_h2); }

__global__ __launch_bounds__(256) void dec3_kernel(const float* __restrict__ W,
                                                   const float* __restrict__ b,
                                                   float* __restrict__ out)
{ gemm_body<1024, 784, 1>(g_h2, W, b, out); }

// =====================================================================
extern "C" void kernel_launch(void* const* d_in, const int* in_sizes, int n_in,
                              void* d_out, int out_size)
{
    const float* input_x = (const float*)d_in[0];
    const float* y       = (const float*)d_in[1];
    const float* conv1_w = (const float*)d_in[2];
    const float* conv1_b = (const float*)d_in[3];
    const float* pc_w    = (const float*)d_in[4];
    const float* pc_b    = (const float*)d_in[5];
    const float* w_pose  = (const float*)d_in[6];
    const float* d1_w    = (const float*)d_in[7];
    const float* d1_b    = (const float*)d_in[8];
    const float* d2_w    = (const float*)d_in[9];
    const float* d2_b    = (const float*)d_in[10];
    const float* d3_w    = (const float*)d_in[11];
    const float* d3_b    = (const float*)d_in[12];
    float* out = (float*)d_out;

    cudaFuncSetAttribute(pc_kernel, cudaFuncAttributeMaxDynamicSharedMemorySize,
                         PC_NSTAGE * PC_STAGE);

    init_kernel<<<1, 1>>>();
    conv1_maxB_kernel<<<640, 256>>>(input_x, conv1_w, conv1_b, pc_w);
    quant_kernel<<<30784, 256>>>(pc_w);
    pc_kernel<<<dim3(72, 2), 512, PC_NSTAGE * PC_STAGE>>>(pc_b);
    uhat_kernel<<<1152, 320>>>(w_pose);
    routing_kernel<<<BATCH, 512>>>(y, out);
    dec1_kernel<<<dim3(8, 8), 256>>>(d1_w, d1_b);
    dec2_kernel<<<dim3(16, 8), 256>>>(d2_w, d2_b);
    dec3_kernel<<<dim3(13, 8), 256>>>(d3_w, d3_b, out + BATCH * 160);
    (void)in_sizes; (void)n_in; (void)out_size;
}